// round 17
// baseline (speedup 1.0000x reference)
#include <cuda_runtime.h>
#include <cuda_fp16.h>
#include <cstdint>

#define LL 1024
#define BB 16
#define XD 512
#define YD 512
#define QDIM 64
#define ND 4
#define HL 128
#define MTOT (LL*BB)
#define RSQRT512 0.04419417382415922f

// -------- scratch (device globals; no allocation allowed) --------
__device__ __half g_Xh [MTOT*XD];
__device__ __half g_Wqh[ND*QDIM*XD];
__device__ __half g_Whh[HL*XD];
__device__ __half g_Wsh[YD*HL];
__device__ __half g_Qh [ND*BB*LL*QDIM];       // [d][b][l][q]
__device__ float  g_sq [ND*BB*LL];
__device__ __half g_hh [MTOT*HL];
__device__ __half g_SinT[(size_t)BB*YD*LL];   // [b][y][l]
__device__ __half g_E  [(size_t)BB*LL*LL];    // [b][i][j]
__device__ float  g_R  [BB*LL];
__device__ float  g_TQp[BB*8*QDIM];
// dependency counters
__device__ int g_hdone, g_qdone, g_adone;
__device__ int g_sdone[4];
__device__ int g_edone[16];

__device__ __forceinline__ void cp16(void* dst, const void* src) {
    uint32_t d = (uint32_t)__cvta_generic_to_shared(dst);
    asm volatile("cp.async.cg.shared.global [%0], [%1], 16;" :: "r"(d), "l"(src));
}
#define CP_COMMIT asm volatile("cp.async.commit_group;")
#define CP_WAIT0  asm volatile("cp.async.wait_group 0;")
#define CP_WAIT1  asm volatile("cp.async.wait_group 1;")

__device__ __forceinline__ float sqrt_ap(float f) {
    float r; asm("sqrt.approx.f32 %0, %1;" : "=f"(r) : "f"(f)); return r;
}
__device__ __forceinline__ void ldsm4(uint32_t r[4], uint32_t addr) {
    asm volatile("ldmatrix.sync.aligned.m8n8.x4.shared.b16 {%0,%1,%2,%3}, [%4];"
        : "=r"(r[0]), "=r"(r[1]), "=r"(r[2]), "=r"(r[3]) : "r"(addr));
}
__device__ __forceinline__ void mma_f16(float c[4], const uint32_t a[4],
                                        uint32_t b0, uint32_t b1) {
    asm volatile("mma.sync.aligned.m16n8k16.row.col.f32.f16.f16.f32 "
        "{%0,%1,%2,%3}, {%4,%5,%6,%7}, {%8,%9}, {%0,%1,%2,%3};"
        : "+f"(c[0]), "+f"(c[1]), "+f"(c[2]), "+f"(c[3])
        : "r"(a[0]), "r"(a[1]), "r"(a[2]), "r"(a[3]), "r"(b0), "r"(b1));
}

// producer release / consumer acquire
__device__ __forceinline__ void mark(int* p) {
    __syncthreads();
    __threadfence();
    if (threadIdx.x == 0) atomicAdd(p, 1);
}
__device__ __forceinline__ void spin1(const int* p, int target) {
    if (threadIdx.x == 0) {
        volatile const int* vp = p;
        while (*vp < target) __nanosleep(128);
    }
    __syncthreads();
}

// ---------------- unified fp16 BT GEMM mainloop ----------------
#define F16_STAGE 32768
template<int NCH>
__device__ __forceinline__ void gemm_f16(const __half* __restrict__ A, int lda,
                                         const __half* __restrict__ Bg, int ldb,
                                         float acc[2][8][4], char* sm, uint32_t smU)
{
    const int tid = threadIdx.x;
    const int lane = tid & 31, warp = tid >> 5;
    const int wm = (warp & 3) * 32, wn = (warp >> 2) * 64;
    const int la7 = lane & 7, hi = (lane >> 4) & 1;

    #define GLD(s, k0) do {                                                          \
        char* st_ = sm + (s)*F16_STAGE;                                              \
        _Pragma("unroll")                                                            \
        for (int i_ = 0; i_ < 8; i_++) {                                             \
            int u_ = tid + i_*256;                                                   \
            if (u_ < 1024) {                                                         \
                int row_ = u_ >> 3, c_ = u_ & 7;                                     \
                cp16(st_ + row_*128 + ((c_ ^ (row_ & 7)) << 4),                      \
                     A + (size_t)row_*lda + (k0) + c_*8);                            \
            } else {                                                                 \
                int v_ = u_ - 1024;                                                  \
                int row_ = v_ >> 3, c_ = v_ & 7;                                     \
                cp16(st_ + 16384 + row_*128 + ((c_ ^ (row_ & 7)) << 4),              \
                     Bg + (size_t)row_*ldb + (k0) + c_*8);                           \
            }                                                                        \
        }                                                                            \
        CP_COMMIT;                                                                   \
    } while (0)

    GLD(0, 0);
    if (NCH > 1) GLD(1, 64);
    for (int t = 0; t < NCH; t++) {
        if (t + 1 < NCH) { CP_WAIT1; } else { CP_WAIT0; }
        __syncthreads();
        if (t + 2 < NCH) GLD((t + 2) % 3, (t + 2) * 64);
        const uint32_t aB = smU + (t % 3) * F16_STAGE;
        const uint32_t bB = aB + 16384;
        #pragma unroll
        for (int kk = 0; kk < 4; kk++) {
            uint32_t af[2][4];
            #pragma unroll
            for (int m = 0; m < 2; m++) {
                int row = wm + m*16 + (lane & 15);
                ldsm4(af[m], aB + row*128 + (((kk*2 + hi) ^ (row & 7)) << 4));
            }
            uint32_t bf[4][4];
            #pragma unroll
            for (int p = 0; p < 4; p++) {
                int row = wn + p*16 + la7 + (lane & 8);
                ldsm4(bf[p], bB + row*128 + (((kk*2 + hi) ^ (row & 7)) << 4));
            }
            #pragma unroll
            for (int m = 0; m < 2; m++)
                #pragma unroll
                for (int n = 0; n < 8; n++)
                    mma_f16(acc[m][n], af[m], bf[n>>1][n&1], bf[n>>1][(n&1)+2]);
        }
    }
    #undef GLD
}
#define F16_SMEM (3*F16_STAGE)

// ============================================================
// kfront: X fp32->fp16 (blocks 0..8191) + weights + R-zero + counters
// ============================================================
__global__ void kfront(const float* __restrict__ X, const float* __restrict__ Wq,
                       const float* __restrict__ Wh, const float* __restrict__ Ws) {
    const int bid = blockIdx.x;
    if (bid == 8192 && threadIdx.x < 32) {
        int t = threadIdx.x;
        if (t == 0) { g_hdone = 0; g_qdone = 0; g_adone = 0; }
        if (t < 4)  g_sdone[t] = 0;
        if (t < 16) g_edone[t] = 0;
    }
    if (bid < 8192) {
        int i = (bid * 256 + threadIdx.x) * 4;
        float4 v = *(const float4*)(X + i);
        *(__half2*)(g_Xh + i)     = __floats2half2_rn(v.x, v.y);
        *(__half2*)(g_Xh + i + 2) = __floats2half2_rn(v.z, v.w);
        return;
    }
    int i = ((bid - 8192) * 256 + threadIdx.x) * 4;
    const float* s; __half* d; int j;
    if (i < 131072)      { s = Wq; d = g_Wqh; j = i; }
    else if (i < 196608) { s = Wh; d = g_Whh; j = i - 131072; }
    else if (i < 262144) { s = Ws; d = g_Wsh; j = i - 196608; }
    else if (i < 278528) { j = i - 262144; *(float4*)&g_R[j] = make_float4(0,0,0,0); return; }
    else return;
    float4 v = *(const float4*)(s + j);
    *(__half2*)(d + j)     = __floats2half2_rn(v.x, v.y);
    *(__half2*)(d + j + 2) = __floats2half2_rn(v.z, v.w);
}

// ============================================================
// role bodies
// ============================================================
__device__ __forceinline__ void k1f_body(int x, int row0, const float* __restrict__ bq,
                                         const float* __restrict__ bh,
                                         char* sm, uint32_t smU) {
    const __half* A  = g_Xh + (size_t)row0 * XD;
    const __half* Bg = (x < 2) ? g_Wqh + (size_t)x * 128 * XD : g_Whh;
    float acc[2][8][4] = {};
    gemm_f16<XD/64>(A, XD, Bg, XD, acc, sm, smU);
    const int lane = threadIdx.x & 31, warp = threadIdx.x >> 5;
    const int wm = (warp & 3) * 32, wn = (warp >> 2) * 64;
    const int qr = lane >> 2, qc = lane & 3;
    if (x < 2) {
        const int col0 = x * 128;
        const int d = (col0 + wn) >> 6;
        #pragma unroll
        for (int m = 0; m < 2; m++)
            #pragma unroll
            for (int rr = 0; rr < 2; rr++) {
                int mrow = row0 + wm + m*16 + qr + rr*8;
                int l = mrow >> 4, b = mrow & 15;
                float s = 0.f;
                #pragma unroll
                for (int n = 0; n < 8; n++) {
                    int cg = col0 + wn + n*8 + 2*qc;
                    int q = cg & 63;
                    __half2 hv = __floats2half2_rn(acc[m][n][rr*2+0] + bq[cg],
                                                   acc[m][n][rr*2+1] + bq[cg+1]);
                    float vx = __half2float(__low2half(hv));
                    float vy = __half2float(__high2half(hv));
                    s += vx*vx + vy*vy;
                    *(__half2*)&g_Qh[(((size_t)d*BB + b)*LL + l)*QDIM + q] = hv;
                }
                s += __shfl_xor_sync(0xffffffffu, s, 1);
                s += __shfl_xor_sync(0xffffffffu, s, 2);
                if (qc == 0) g_sq[((size_t)d*BB + b)*LL + l] = s;
            }
        mark(&g_qdone);
    } else {
        #pragma unroll
        for (int m = 0; m < 2; m++)
            #pragma unroll
            for (int rr = 0; rr < 2; rr++) {
                int mrow = row0 + wm + m*16 + qr + rr*8;
                #pragma unroll
                for (int n = 0; n < 8; n++) {
                    int cg = wn + n*8 + 2*qc;
                    float v0 = 1.f / (1.f + __expf(-(acc[m][n][rr*2+0] + bh[cg])));
                    float v1 = 1.f / (1.f + __expf(-(acc[m][n][rr*2+1] + bh[cg+1])));
                    *(__half2*)&g_hh[(size_t)mrow * HL + cg] = __floats2half2_rn(v0, v1);
                }
            }
        mark(&g_hdone);
    }
}

#define TLD 136
__device__ __forceinline__ void k2b_body(int colT, int rowT, const float* __restrict__ bs,
                                         char* sm, uint32_t smU) {
    spin1(&g_hdone, 128);
    const int row0 = rowT * 128, col0 = colT * 128;
    float acc[2][8][4] = {};
    gemm_f16<HL/64>(g_hh + (size_t)row0 * HL, HL, g_Wsh + (size_t)col0 * HL, HL, acc, sm, smU);
    const int tid = threadIdx.x;
    const int lane = tid & 31, warp = tid >> 5;
    const int wm = (warp & 3) * 32, wn = (warp >> 2) * 64;
    const int qr = lane >> 2, qc = lane & 3;
    __syncthreads();
    __half* T = (__half*)sm;
    #pragma unroll
    for (int m = 0; m < 2; m++)
        #pragma unroll
        for (int rr = 0; rr < 2; rr++) {
            int mr = wm + m*16 + qr + rr*8;
            #pragma unroll
            for (int n = 0; n < 8; n++) {
                int cc = wn + n*8 + 2*qc;
                T[cc*TLD + mr]     = __float2half(acc[m][n][rr*2+0] + bs[col0 + cc]);
                T[(cc+1)*TLD + mr] = __float2half(acc[m][n][rr*2+1] + bs[col0 + cc + 1]);
            }
        }
    __syncthreads();
    const int l0 = row0 >> 4;
    #pragma unroll
    for (int r = 0; r < 8; r++) {
        int idx = tid + r*256;
        int b = idx & 15, y = idx >> 4;
        __half tmp[8];
        #pragma unroll
        for (int lo = 0; lo < 8; lo++) tmp[lo] = T[y*TLD + lo*16 + b];
        *(uint4*)&g_SinT[((size_t)b*YD + col0 + y)*LL + l0] = *(uint4*)tmp;
    }
    mark(&g_sdone[colT]);
}

__device__ __forceinline__ void k5a_body(int b, int lc, char* sm) {
    spin1(&g_qdone, 256);
    const int t = threadIdx.x;
    const int q = t & 63, part = t >> 6;
    float s = 0.f;
    #pragma unroll
    for (int d = 0; d < ND; d++) {
        const __half* base = g_Qh + (((size_t)d*BB + b)*LL + lc*128) * QDIM;
        for (int l = part; l < 128; l += 4) s += __half2float(base[(size_t)l * QDIM + q]);
    }
    float* red = (float*)sm;
    red[t] = s;
    __syncthreads();
    if (part == 0)
        g_TQp[(b*8 + lc)*QDIM + q] = red[q] + red[64+q] + red[128+q] + red[192+q];
    mark(&g_adone);
}

#define K3_STAGE 24576
__device__ __forceinline__ void k3_body(int jT, int iT, int bI,
                                        const float* __restrict__ mask,
                                        char* sm3, uint32_t smU) {
    spin1(&g_qdone, 256);
    const int i0 = iT * 128, j0 = jT * 64;
    const int tid = threadIdx.x;
    const int lane = tid & 31, warp = tid >> 5;
    const int wm = (warp & 3) * 32, wn = (warp >> 2) * 32;
    const int qr = lane >> 2, qc = lane & 3;

    #define K3_LD(s, d_) do {                                                        \
        const __half* Ab_ = g_Qh + (((size_t)(d_)*BB + bI)*LL + i0) * QDIM;          \
        const __half* Bb_ = g_Qh + (((size_t)(d_)*BB + bI)*LL + j0) * QDIM;          \
        char* st_ = sm3 + (s)*K3_STAGE;                                              \
        _Pragma("unroll")                                                            \
        for (int i_ = 0; i_ < 6; i_++) {                                             \
            int u_ = tid + i_*256;                                                   \
            if (u_ < 1024) {                                                         \
                int row_ = u_ >> 3, c_ = u_ & 7;                                     \
                cp16(st_ + row_*128 + ((c_ ^ (row_ & 7)) << 4),                      \
                     Ab_ + (size_t)row_*QDIM + c_*8);                                \
            } else {                                                                 \
                int v_ = u_ - 1024;                                                  \
                int row_ = v_ >> 3, c_ = v_ & 7;                                     \
                cp16(st_ + 16384 + row_*128 + ((c_ ^ (row_ & 7)) << 4),              \
                     Bb_ + (size_t)row_*QDIM + c_*8);                                \
            }                                                                        \
        }                                                                            \
        CP_COMMIT;                                                                   \
    } while (0)

    float logit[2][4][4] = {};
    K3_LD(0, 0);
    K3_LD(1, 1);
    const int la7 = lane & 7, hi = (lane >> 4) & 1;
    for (int d = 0; d < ND; d++) {
        if (d + 1 < ND) { CP_WAIT1; } else { CP_WAIT0; }
        __syncthreads();
        if (d + 2 < ND) K3_LD((d + 2) % 3, d + 2);
        const uint32_t aB = smU + (d % 3) * K3_STAGE;
        const uint32_t bB = aB + 16384;
        float acc[2][4][4] = {};
        #pragma unroll
        for (int kk = 0; kk < 4; kk++) {
            int sw = ((kk*2 + hi) ^ la7) << 4;
            uint32_t af[2][4];
            #pragma unroll
            for (int m = 0; m < 2; m++) {
                int row = wm + m*16 + (lane & 15);
                ldsm4(af[m], aB + row*128 + (((kk*2 + hi) ^ (row & 7)) << 4));
            }
            uint32_t bf[2][4];
            #pragma unroll
            for (int p = 0; p < 2; p++) {
                int row = wn + p*16 + la7 + (lane & 8);
                ldsm4(bf[p], bB + row*128 + sw);
            }
            #pragma unroll
            for (int m = 0; m < 2; m++)
                #pragma unroll
                for (int n = 0; n < 4; n++)
                    mma_f16(acc[m][n], af[m], bf[n>>1][n&1], bf[n>>1][(n&1)+2]);
        }
        const float sgn = (d & 1) ? -1.f : 1.f;
        const float* sqb = g_sq + ((size_t)d*BB + bI) * LL;
        #pragma unroll
        for (int m = 0; m < 2; m++)
            #pragma unroll
            for (int rr = 0; rr < 2; rr++) {
                int gi = i0 + wm + m*16 + qr + rr*8;
                float sqi = sqb[gi];
                #pragma unroll
                for (int n = 0; n < 4; n++) {
                    int gj = j0 + wn + n*8 + 2*qc;
                    float d20 = fmaxf(sqi + sqb[gj]   - 2.f*acc[m][n][rr*2+0], 0.f);
                    float d21 = fmaxf(sqi + sqb[gj+1] - 2.f*acc[m][n][rr*2+1], 0.f);
                    logit[m][n][rr*2+0] += (gi == gj)   ? 0.f : sgn * sqrt_ap(d20);
                    logit[m][n][rr*2+1] += (gi == gj+1) ? 0.f : sgn * sqrt_ap(d21);
                }
            }
    }
    #undef K3_LD
    #pragma unroll
    for (int m = 0; m < 2; m++)
        #pragma unroll
        for (int rr = 0; rr < 2; rr++) {
            int gi = i0 + wm + m*16 + qr + rr*8;
            float s = 0.f;
            #pragma unroll
            for (int n = 0; n < 4; n++) {
                int gj = j0 + wn + n*8 + 2*qc;
                float2 mv = *(const float2*)&mask[(size_t)gi * LL + gj];
                float e0 = __expf(logit[m][n][rr*2+0] * RSQRT512 + mv.x);
                float e1 = __expf(logit[m][n][rr*2+1] * RSQRT512 + mv.y);
                __half2 p2 = __floats2half2_rn(e0, e1);
                s += __half2float(__low2half(p2)) + __half2float(__high2half(p2));
                *(__half2*)&g_E[((size_t)bI*LL + gi)*LL + gj] = p2;
            }
            s += __shfl_xor_sync(0xffffffffu, s, 1);
            s += __shfl_xor_sync(0xffffffffu, s, 2);
            if (qc == 0) atomicAdd(&g_R[bI*LL + gi], s);
        }
    mark(&g_edone[bI]);
}

__device__ __forceinline__ void k4_body(int b, int colT, int rowT,
                                        float* __restrict__ out,
                                        char* sm, uint32_t smU) {
    if (threadIdx.x == 0) {
        volatile const int* ve = &g_edone[b];
        volatile const int* vs = &g_sdone[colT];
        while (*ve < 128) __nanosleep(128);
        while (*vs < 128) __nanosleep(128);
    }
    __syncthreads();
    const int row0 = rowT * 128, col0 = colT * 128;
    float acc[2][8][4] = {};
    gemm_f16<LL/64>(g_E + (size_t)b*LL*LL + (size_t)row0*LL, LL,
                    g_SinT + ((size_t)b*YD + col0)*LL, LL, acc, sm, smU);
    const int lane = threadIdx.x & 31, warp = threadIdx.x >> 5;
    const int wm = (warp & 3) * 32, wn = (warp >> 2) * 64;
    const int qr = lane >> 2, qc = lane & 3;
    #pragma unroll
    for (int m = 0; m < 2; m++)
        #pragma unroll
        for (int rr = 0; rr < 2; rr++) {
            int row = row0 + wm + m*16 + qr + rr*8;
            float rinv = 1.f / g_R[b*LL + row];
            #pragma unroll
            for (int n = 0; n < 8; n++) {
                int col = col0 + wn + n*8 + 2*qc;
                float2 v;
                v.x = acc[m][n][rr*2+0] * rinv;
                v.y = acc[m][n][rr*2+1] * rinv;
                *(float2*)&out[((size_t)b*LL + row)*YD + col] = v;
            }
        }
}

// ============================================================
// kmain: [0,256) k1f-Q | [256,384) k1f-h | [384,896) k2b | [896,1024) k5a |
//        [1024,3584) per-b {128 k3 + 32 k4} | [3584,3588) k5b
// ============================================================
__global__ __launch_bounds__(256, 2) void kmain(const float* __restrict__ mask,
                                                const float* __restrict__ bq,
                                                const float* __restrict__ bh,
                                                const float* __restrict__ bs,
                                                float* __restrict__ out) {
    extern __shared__ char sm[];
    const uint32_t smU = (uint32_t)__cvta_generic_to_shared(sm);
    const int bid = blockIdx.x;
    if (bid < 384) {
        int x = bid >> 7, rowT = bid & 127;
        k1f_body(x, rowT * 128, bq, bh, sm, smU);
    } else if (bid < 896) {
        int t = bid - 384;
        k2b_body(t & 3, t >> 2, bs, sm, smU);
    } else if (bid < 1024) {
        int t = bid - 896;
        k5a_body(t & 15, t >> 4, sm);
    } else if (bid < 3584) {
        int t = bid - 1024;
        int b = t / 160, u = t - b * 160;
        if (u < 128) k3_body(u & 15, u >> 4, b, mask, sm, smU);
        else { int u2 = u - 128; k4_body(b, u2 & 3, (u2 >> 2) & 7, out, sm, smU); }
    } else {
        spin1(&g_adone, 128);
        int idx = (bid - 3584) * 256 + threadIdx.x;   // 0..1023
        int b = idx >> 6, q = idx & 63;
        float s = 0.f;
        #pragma unroll
        for (int lc = 0; lc < 8; lc++) s += g_TQp[(b*8 + lc)*QDIM + q];
        out[(size_t)BB*LL*YD + b*QDIM + q] = s * (1.f / (ND * (float)LL));
    }
}

// ============================================================
extern "C" void kernel_launch(void* const* d_in, const int* in_sizes, int n_in,
                              void* d_out, int out_size) {
    const float* X    = (const float*)d_in[0];
    const float* mask = (const float*)d_in[1];
    const float* Wq   = (const float*)d_in[2];
    const float* bq   = (const float*)d_in[3];
    const float* Wh   = (const float*)d_in[4];
    const float* bh   = (const float*)d_in[5];
    const float* Ws   = (const float*)d_in[6];
    const float* bs   = (const float*)d_in[7];
    float* out = (float*)d_out;

    cudaFuncSetAttribute(kmain, cudaFuncAttributeMaxDynamicSharedMemorySize, F16_SMEM);

    kfront<<<8464, 256>>>(X, Wq, Wh, Ws);
    kmain<<<3588, 256, F16_SMEM>>>(mask, bq, bh, bs, out);
}